// round 11
// baseline (speedup 1.0000x reference)
#include <cuda_runtime.h>
#include <cstdint>

#define HH 128
#define WW 128
#define CC 392
#define KPOOL 7
#define KK 49
#define MAXN 2048

#define CPAD 416              // channels padded (13 x 32)
#define PFW 130               // padded spatial (halo 1)
#define KTOT (9 * CPAD)       // 3744
#define NCH 117               // 9 taps * 13 ci-blocks of 32

#define NTILES 896            // 128 M-tiles (rows) x 7 N-tiles (56)
#define GRID 296              // 148 SMs x 2 CTAs

// smem per stage (bytes): A_h[128*32] A_l[128*32] B_h[56*32] B_l[56*32]
#define ST_AH 0
#define ST_AL 4096
#define ST_BH 8192
#define ST_BL 9984
#define STAGE_BYTES 11776
#define SMEM_BYTES (3 * STAGE_BYTES)

// ---------------------------------------------------------------------------
// Device scratch (no allocation allowed)
// ---------------------------------------------------------------------------
__device__ int8_t g_pf_h[PFW * PFW * CPAD];
__device__ int8_t g_pf_l[PFW * PFW * CPAD];
__device__ int8_t g_wt_h[CC * KTOT];      // [n][k]
__device__ int8_t g_wt_l[CC * KTOT];
__device__ int    g_maxbits[2];           // abs-max of features / weights (float bits)
__device__ float  g_map[HH * WW * CC];
__device__ float  g_off[MAXN * KK * 8];

// ---------------------------------------------------------------------------
// PTX helpers (sm_75/80-era — safe for compute_103)
// ---------------------------------------------------------------------------
__device__ __forceinline__ uint32_t smem_u32(const void* p) {
    uint32_t a;
    asm("{ .reg .u64 t; cvta.to.shared.u64 t, %1; cvt.u32.u64 %0, t; }" : "=r"(a) : "l"(p));
    return a;
}
#define CP16(dst, src) \
    asm volatile("cp.async.cg.shared.global [%0], [%1], 16;" :: "r"(dst), "l"(src))
#define CP_COMMIT() asm volatile("cp.async.commit_group;" ::: "memory")
#define CP_WAIT2() asm volatile("cp.async.wait_group 2;" ::: "memory")
#define CP_WAIT1() asm volatile("cp.async.wait_group 1;" ::: "memory")
#define CP_WAIT0() asm volatile("cp.async.wait_group 0;" ::: "memory")

#define LDSM4(r, a) \
    asm volatile("ldmatrix.sync.aligned.m8n8.x4.shared.b16 {%0,%1,%2,%3}, [%4];" \
        : "=r"((r)[0]), "=r"((r)[1]), "=r"((r)[2]), "=r"((r)[3]) : "r"(a))
#define LDSM2(r0, r1, a) \
    asm volatile("ldmatrix.sync.aligned.m8n8.x2.shared.b16 {%0,%1}, [%2];" \
        : "=r"(r0), "=r"(r1) : "r"(a))

// int8 IMMA: D(s32) = A(s8,16x32) * B(s8,32x8) + C
#define MMA_I(ar, b0, b1, cc) \
    asm volatile("mma.sync.aligned.m16n8k32.row.col.s32.s8.s8.s32 " \
        "{%0,%1,%2,%3}, {%4,%5,%6,%7}, {%8,%9}, {%0,%1,%2,%3};" \
        : "+r"((cc)[0]), "+r"((cc)[1]), "+r"((cc)[2]), "+r"((cc)[3]) \
        : "r"((ar)[0]), "r"((ar)[1]), "r"((ar)[2]), "r"((ar)[3]), "r"(b0), "r"(b1))

// one A frag (m16,k32) x 7 n8 frags into given accumulator set
#define PASS_I(A, B, AC) do { \
    MMA_I((A), (B)[0],  (B)[1],  (AC)[0]); \
    MMA_I((A), (B)[2],  (B)[3],  (AC)[1]); \
    MMA_I((A), (B)[4],  (B)[5],  (AC)[2]); \
    MMA_I((A), (B)[6],  (B)[7],  (AC)[3]); \
    MMA_I((A), (B)[8],  (B)[9],  (AC)[4]); \
    MMA_I((A), (B)[10], (B)[11], (AC)[5]); \
    MMA_I((A), (B)[12], (B)[13], (AC)[6]); \
} while (0)

// swizzled smem offset: 32B rows, seg = 16B column (0..1); conflict-free ldmatrix
__device__ __forceinline__ uint32_t swz8(int row, int seg) {
    return (uint32_t)(row * 32 + (((seg ^ (row >> 2)) & 1) << 4));
}

__device__ __forceinline__ void quant16(float v, float inv, int8_t& h, int8_t& l) {
    int q = __float2int_rn(v * inv);
    q = max(-32512, min(32512, q));
    int hh = (q + 128) >> 8;          // round-to-nearest of q/256, hh in [-127,127]
    h = (int8_t)hh;
    l = (int8_t)(q - (hh << 8));      // in [-128,127]
}

// ---------------------------------------------------------------------------
// Precompute 0: reset abs-max slots
// ---------------------------------------------------------------------------
__global__ void init_max_kernel() { g_maxbits[0] = 0; g_maxbits[1] = 0; }

// ---------------------------------------------------------------------------
// Precompute 1: abs-max reduction (float bits; atomicMax valid for >=0 floats)
// ---------------------------------------------------------------------------
__global__ __launch_bounds__(256) void absmax_kernel(const float* __restrict__ p, int n, int slot)
{
    __shared__ float red[256];
    float m = 0.f;
    for (int i = blockIdx.x * 256 + threadIdx.x; i < n; i += gridDim.x * 256)
        m = fmaxf(m, fabsf(p[i]));
    red[threadIdx.x] = m;
    __syncthreads();
    for (int s = 128; s > 0; s >>= 1) {
        if (threadIdx.x < s) red[threadIdx.x] = fmaxf(red[threadIdx.x], red[threadIdx.x + s]);
        __syncthreads();
    }
    if (threadIdx.x == 0) atomicMax(&g_maxbits[slot], __float_as_int(red[0]));
}

// ---------------------------------------------------------------------------
// Precompute 2: pad + 16-bit fixed-point split features -> g_pf_h/l [130,130,416]
// ---------------------------------------------------------------------------
__global__ __launch_bounds__(256) void quant_features(const float* __restrict__ f)
{
    int idx = blockIdx.x * 256 + threadIdx.x;
    const int TOT = PFW * PFW * (CPAD / 4);
    if (idx >= TOT) return;
    float mx = __int_as_float(g_maxbits[0]);
    float inv = (mx > 0.f) ? (32512.f / mx) : 0.f;
    int p = idx / (CPAD / 4);
    int c0 = (idx - p * (CPAD / 4)) * 4;
    int y = p / PFW - 1;
    int x = p - (y + 1) * PFW - 1;
    bool in = ((unsigned)y < HH) && ((unsigned)x < WW);
    int8_t h[4], l[4];
#pragma unroll
    for (int j = 0; j < 4; ++j) {
        int c = c0 + j;
        float v = (in && c < CC) ? __ldg(f + ((size_t)(y * WW + x)) * CC + c) : 0.f;
        quant16(v, inv, h[j], l[j]);
    }
    size_t o = (size_t)p * CPAD + c0;
    *(char4*)(g_pf_h + o) = make_char4(h[0], h[1], h[2], h[3]);
    *(char4*)(g_pf_l + o) = make_char4(l[0], l[1], l[2], l[3]);
}

// ---------------------------------------------------------------------------
// Precompute 3: coalesced transpose + quantize weights -> g_wt_h/l [392][3744]
// w: [tap(9)][ci(392)][co(392)]; k = tap*416 + ci
// ---------------------------------------------------------------------------
__global__ __launch_bounds__(256) void quant_weights(const float* __restrict__ w)
{
    __shared__ float tile[32][33];
    float mx = __int_as_float(g_maxbits[1]);
    float inv = (mx > 0.f) ? (32512.f / mx) : 0.f;
    const int tap = blockIdx.z;
    const int ci0 = blockIdx.x * 32;
    const int n0  = blockIdx.y * 32;
    const int tx = threadIdx.x & 31;
    const int ty = threadIdx.x >> 5;
#pragma unroll
    for (int r = 0; r < 4; ++r) {
        int ci = ci0 + ty + r * 8;
        int n  = n0 + tx;
        float v = 0.f;
        if (ci < CC && n < CC) v = __ldg(w + ((size_t)(tap * CC + ci)) * CC + n);
        tile[ty + r * 8][tx] = v;
    }
    __syncthreads();
#pragma unroll
    for (int r = 0; r < 4; ++r) {
        int n  = n0 + ty + r * 8;
        int ci = ci0 + tx;
        if (n < CC && ci < CPAD) {
            float v = (ci < CC) ? tile[tx][ty + r * 8] : 0.f;
            int8_t h, l;
            quant16(v, inv, h, l);
            size_t o = (size_t)n * KTOT + tap * CPAD + ci;
            g_wt_h[o] = h;
            g_wt_l[o] = l;
        }
    }
}

__global__ __launch_bounds__(256) void pad_weights_tail()
{
    int idx = blockIdx.x * 256 + threadIdx.x;
    const int TOT = CC * 9 * (CPAD - CC);
    if (idx >= TOT) return;
    int n = idx / (9 * (CPAD - CC));
    int rem = idx - n * 9 * (CPAD - CC);
    int tap = rem / (CPAD - CC);
    int ci = CC + rem - tap * (CPAD - CC);
    size_t o = (size_t)n * KTOT + tap * CPAD + ci;
    g_wt_h[o] = 0;
    g_wt_l[o] = 0;
}

// ---------------------------------------------------------------------------
// Conv implicit GEMM on IMMA s8 (m16n8k32). Persistent, tile BM=128 x BN=56,
// 256 threads (8 warps on M, warp tile 16x56). 3 passes: hh (acc_hh),
// lh + hl (shared acc_p). 3-stage cp.async pipeline, round-9 barrier shape.
// ---------------------------------------------------------------------------
__device__ __forceinline__ void issue_chunk(int c, int s, int tid, int y, int n0, uint32_t sm)
{
    int tap = c / 13;
    int ci0 = (c - tap * 13) * 32;
    int dy = tap / 3 - 1;
    int dx = tap - (tap / 3) * 3 - 1;
    uint32_t sbase = sm + s * STAGE_BYTES;
    // A: 128 rows x 32B x 2 mats = 512 x 16B over 256 threads
#pragma unroll
    for (int t = 0; t < 2; ++t) {
        int i = tid + t * 256;
        int mat = i >> 8;
        int r = (i >> 1) & 127;
        int seg = i & 1;
        const int8_t* g = mat ? g_pf_l : g_pf_h;
        const int8_t* src = g
            + ((size_t)((y + dy + 1) * PFW + (r + dx + 1))) * CPAD + ci0 + seg * 16;
        uint32_t dst = sbase + mat * 4096 + swz8(r, seg);
        CP16(dst, src);
    }
    // B: 56 rows x 32B x 2 mats = 224 x 16B
    if (tid < 224) {
        int mat = (tid >= 112);
        int ii = tid - mat * 112;
        int rr = ii >> 1;
        int seg = ii & 1;
        const int8_t* g = mat ? g_wt_l : g_wt_h;
        const int8_t* src = g + (size_t)(n0 + rr) * KTOT + tap * CPAD + ci0 + seg * 16;
        uint32_t dst = sbase + ST_BH + mat * 1792 + swz8(rr, seg);
        CP16(dst, src);
    }
    CP_COMMIT();
}

__global__ void __launch_bounds__(256, 2) conv_mma_kernel()
{
    extern __shared__ char smem[];
    uint32_t sm = smem_u32(smem);
    const int tid  = threadIdx.x;
    const int lane = tid & 31;
    const int wid  = tid >> 5;

    // A ldmatrix lanes: rows = wid*16 + (lane&15), seg = lane>>4
    const int arow = wid * 16 + (lane & 15);
    const int aseg = lane >> 4;
    // B LDSM4 lanes: rows (lane&7) + ((lane>>4)&1)*8, seg (lane>>3)&1
    const int brow = (lane & 7) + ((lane >> 4) & 1) * 8;
    const int bseg = (lane >> 3) & 1;
    // B LDSM2 lanes (0-15 used): rows 48 + (lane&7), seg (lane>>3)&1
    const int b2row = 48 + (lane & 7);

#pragma unroll 1
    for (int tt = blockIdx.x; tt < NTILES; tt += GRID) {
        const int y  = tt / 7;
        const int n0 = (tt - y * 7) * 56;

        int acch[7][4], accp[7][4];
#pragma unroll
        for (int j = 0; j < 7; ++j)
#pragma unroll
            for (int q = 0; q < 4; ++q) { acch[j][q] = 0; accp[j][q] = 0; }

        issue_chunk(0, 0, tid, y, n0, sm);
        issue_chunk(1, 1, tid, y, n0, sm);
        issue_chunk(2, 2, tid, y, n0, sm);

        int s = 0;
#pragma unroll 1
        for (int c = 0; c < NCH; ++c) {
            if (c < NCH - 2)       { CP_WAIT2(); }
            else if (c == NCH - 2) { CP_WAIT1(); }
            else                   { CP_WAIT0(); }
            __syncthreads();
            const uint32_t st = sm + s * STAGE_BYTES;
            const uint32_t Ah = st + ST_AH;
            const uint32_t Al = st + ST_AL;
            const uint32_t Bh = st + ST_BH;
            const uint32_t Bl = st + ST_BL;
            {
                uint32_t ah[4], al[4], bh[14], bl[14];
                const uint32_t aoff = swz8(arow, aseg);
                LDSM4(ah, Ah + aoff);
                LDSM4(&bh[0], Bh + swz8(brow, bseg));
                LDSM4(&bh[4], Bh + swz8(16 + brow, bseg));
                LDSM4(&bh[8], Bh + swz8(32 + brow, bseg));
                LDSM2(bh[12], bh[13], Bh + swz8(b2row, bseg));
                PASS_I(ah, bh, acch);               // h*h -> acc_hh
                LDSM4(al, Al + aoff);
                PASS_I(al, bh, accp);               // l*h -> acc_p
                LDSM4(&bl[0], Bl + swz8(brow, bseg));
                LDSM4(&bl[4], Bl + swz8(16 + brow, bseg));
                LDSM4(&bl[8], Bl + swz8(32 + brow, bseg));
                LDSM2(bl[12], bl[13], Bl + swz8(b2row, bseg));
                PASS_I(ah, bl, accp);               // h*l -> acc_p
            }
            __syncthreads();
            if (c + 3 < NCH) issue_chunk(c + 3, s, tid, y, n0, sm);
            s = (s == 2) ? 0 : s + 1;
        }

        // epilogue: combine fixed-point parts -> fp32 g_map
        {
            float sf = __int_as_float(g_maxbits[0]) * (1.f / 32512.f);
            float sw = __int_as_float(g_maxbits[1]) * (1.f / 32512.f);
            float sc = sf * sw;
            const int nlane = n0 + (lane & 3) * 2;
#pragma unroll
            for (int h = 0; h < 2; ++h) {
                const int x = wid * 16 + (lane >> 2) + h * 8;
                float* op = g_map + ((size_t)(y * WW + x)) * CC;
#pragma unroll
                for (int j = 0; j < 7; ++j) {
                    float v0 = sc * (65536.f * (float)acch[j][h * 2]
                                   + 256.f  * (float)accp[j][h * 2]);
                    float v1 = sc * (65536.f * (float)acch[j][h * 2 + 1]
                                   + 256.f  * (float)accp[j][h * 2 + 1]);
                    *(float2*)(op + nlane + j * 8) = make_float2(v0, v1);
                }
            }
        }
    }
}

// ---------------------------------------------------------------------------
// Kernel: PS-RoI pool of conv map -> per-bin offsets (feature coords)
// ---------------------------------------------------------------------------
__global__ __launch_bounds__(256) void offset_pool_kernel(const float* __restrict__ rois, int N)
{
    int idx = blockIdx.x * blockDim.x + threadIdx.x;
    if (idx >= N * KK) return;
    int n   = idx / KK;
    int bin = idx - n * KK;
    int bi  = bin / KPOOL;
    int bj  = bin - bi * KPOOL;

    const float* r = rois + n * 5;
    float r1 = r[1], r2 = r[2], r3 = r[3], r4 = r[4];
    float x1 = r1 * 0.0625f;
    float y1 = r2 * 0.0625f;
    float x2 = (r3 + 1.0f) * 0.0625f;
    float y2 = (r4 + 1.0f) * 0.0625f;
    float bw = (x2 - x1) / 7.0f;
    float bh = (y2 - y1) / 7.0f;
    float cx = x1 + ((float)bj + 0.5f) * bw;
    float cy = y1 + ((float)bi + 0.5f) * bh;

    float y0f = floorf(cy), x0f = floorf(cx);
    float wy = cy - y0f,    wx = cx - x0f;
    int iy0 = min(max((int)y0f, 0), HH - 1);
    int iy1 = min(max((int)y0f + 1, 0), HH - 1);
    int ix0 = min(max((int)x0f, 0), WW - 1);
    int ix1 = min(max((int)x0f + 1, 0), WW - 1);

    float w00 = (1.f - wy) * (1.f - wx);
    float w01 = (1.f - wy) * wx;
    float w10 = wy * (1.f - wx);
    float w11 = wy * wx;

    const float* p00 = g_map + ((size_t)(iy0 * WW + ix0)) * CC + bin * 8;
    const float* p01 = g_map + ((size_t)(iy0 * WW + ix1)) * CC + bin * 8;
    const float* p10 = g_map + ((size_t)(iy1 * WW + ix0)) * CC + bin * 8;
    const float* p11 = g_map + ((size_t)(iy1 * WW + ix1)) * CC + bin * 8;

    float rw = r3 - r1 + 1.0f;
    float rh = r4 - r2 + 1.0f;

    float* o = g_off + (size_t)idx * 8;
#pragma unroll
    for (int g = 0; g < 4; ++g) {
        int d0 = g * 2, d1 = g * 2 + 1;
        float px = w00 * p00[d0] + w01 * p01[d0] + w10 * p10[d0] + w11 * p11[d0];
        float py = w00 * p00[d1] + w01 * p01[d1] + w10 * p10[d1] + w11 * p11[d1];
        o[d0] = (px * rw) * 0.1f * 0.0625f;
        o[d1] = (py * rh) * 0.1f * 0.0625f;
    }
}

// ---------------------------------------------------------------------------
// Kernel: deformable PS-RoI pool of raw features -> output [N,8,7,7]
// ---------------------------------------------------------------------------
__global__ __launch_bounds__(256) void deform_pool_kernel(const float* __restrict__ f,
                                                          const float* __restrict__ rois,
                                                          float* __restrict__ out, int N)
{
    int idx = blockIdx.x * blockDim.x + threadIdx.x;
    if (idx >= N * KK * 8) return;
    int d   = idx & 7;
    int nb  = idx >> 3;
    int n   = nb / KK;
    int bin = nb - n * KK;
    int bi  = bin / KPOOL;
    int bj  = bin - bi * KPOOL;

    const float* r = rois + n * 5;
    float x1 = r[1] * 0.0625f;
    float y1 = r[2] * 0.0625f;
    float x2 = (r[3] + 1.0f) * 0.0625f;
    float y2 = (r[4] + 1.0f) * 0.0625f;
    float bw = (x2 - x1) / 7.0f;
    float bh = (y2 - y1) / 7.0f;
    float cx = x1 + ((float)bj + 0.5f) * bw;
    float cy = y1 + ((float)bi + 0.5f) * bh;

    int g = d >> 1;
    const float* o = g_off + (size_t)nb * 8 + g * 2;
    float sx = cx + o[0];
    float sy = cy + o[1];

    float y0f = floorf(sy), x0f = floorf(sx);
    float wy = sy - y0f,    wx = sx - x0f;
    int iy0 = min(max((int)y0f, 0), HH - 1);
    int iy1 = min(max((int)y0f + 1, 0), HH - 1);
    int ix0 = min(max((int)x0f, 0), WW - 1);
    int ix1 = min(max((int)x0f + 1, 0), WW - 1);

    int ch = bin * 8 + d;
    float v00 = __ldg(f + ((size_t)(iy0 * WW + ix0)) * CC + ch);
    float v01 = __ldg(f + ((size_t)(iy0 * WW + ix1)) * CC + ch);
    float v10 = __ldg(f + ((size_t)(iy1 * WW + ix0)) * CC + ch);
    float v11 = __ldg(f + ((size_t)(iy1 * WW + ix1)) * CC + ch);

    float val = (1.f - wy) * (1.f - wx) * v00 + (1.f - wy) * wx * v01
              + wy * (1.f - wx) * v10 + wy * wx * v11;

    out[((size_t)n * 8 + d) * KK + bin] = val;
}

// ---------------------------------------------------------------------------
extern "C" void kernel_launch(void* const* d_in, const int* in_sizes, int n_in,
                              void* d_out, int out_size)
{
    const float* features = (const float*)d_in[0];  // [1,128,128,392]
    const float* rois     = (const float*)d_in[1];  // [N,5]
    const float* conv_w   = (const float*)d_in[2];  // [3,3,392,392]
    float* out = (float*)d_out;
    int N = in_sizes[1] / 5;

    cudaFuncSetAttribute(conv_mma_kernel, cudaFuncAttributeMaxDynamicSharedMemorySize, SMEM_BYTES);

    // scales (deterministic: atomicMax over float bits, reset every launch)
    init_max_kernel<<<1, 1>>>();
    absmax_kernel<<<512, 256>>>(features, in_sizes[0], 0);
    absmax_kernel<<<256, 256>>>(conv_w, in_sizes[2], 1);

    // quantize + pad
    {
        int tot = PFW * PFW * (CPAD / 4);
        quant_features<<<(tot + 255) / 256, 256>>>(features);
        dim3 gw(13, 13, 9);
        quant_weights<<<gw, 256>>>(conv_w);
        int pt = CC * 9 * (CPAD - CC);
        pad_weights_tail<<<(pt + 255) / 256, 256>>>();
    }

    conv_mma_kernel<<<GRID, 256, SMEM_BYTES>>>();

    int t2 = N * KK;
    offset_pool_kernel<<<(t2 + 255) / 256, 256>>>(rois, N);

    int t3 = N * KK * 8;
    deform_pool_kernel<<<(t3 + 255) / 256, 256>>>(features, rois, out, N);
}

// round 12
// speedup vs baseline: 2.4621x; 2.4621x over previous
#include <cuda_runtime.h>
#include <cuda_bf16.h>
#include <cstdint>

#define HH 128
#define WW 128
#define CC 392
#define KPOOL 7
#define KK 49
#define MAXN 2048

#define CPAD 416              // channels padded (13 x 32)
#define PFW 130               // padded spatial (halo 1)
#define KTOT (9 * CPAD)       // 3744
#define NCH 117               // 9 taps * 13 ci-blocks of 32

#define NTILES 896            // 128 M-tiles (rows) x 7 N-tiles (56)
#define GRID 444              // 148 SMs x 3 CTAs

// smem per stage (bytes): A_hi[128*64] A_lo[128*64] B_hi[56*64] B_lo[56*64]
#define ST_AHI 0
#define ST_ALO 8192
#define ST_BHI 16384
#define ST_BLO 19968
#define STAGE_BYTES 23552
#define SMEM_BYTES (3 * STAGE_BYTES)

// ---------------------------------------------------------------------------
// Device scratch (no allocation allowed)
// ---------------------------------------------------------------------------
__device__ __nv_bfloat16 g_pf_hi[PFW * PFW * CPAD];
__device__ __nv_bfloat16 g_pf_lo[PFW * PFW * CPAD];
__device__ __nv_bfloat16 g_wt_hi[CC * KTOT];      // [n][k]
__device__ __nv_bfloat16 g_wt_lo[CC * KTOT];
__device__ float g_map[HH * WW * CC];
__device__ float g_off[MAXN * KK * 8];

// ---------------------------------------------------------------------------
// PTX helpers (baseline sm_80-era — safe for compute_103)
// ---------------------------------------------------------------------------
__device__ __forceinline__ uint32_t smem_u32(const void* p) {
    uint32_t a;
    asm("{ .reg .u64 t; cvta.to.shared.u64 t, %1; cvt.u32.u64 %0, t; }" : "=r"(a) : "l"(p));
    return a;
}
#define CP16(dst, src) \
    asm volatile("cp.async.cg.shared.global [%0], [%1], 16;" :: "r"(dst), "l"(src))
#define CP_COMMIT() asm volatile("cp.async.commit_group;" ::: "memory")
#define CP_WAIT2() asm volatile("cp.async.wait_group 2;" ::: "memory")
#define CP_WAIT1() asm volatile("cp.async.wait_group 1;" ::: "memory")
#define CP_WAIT0() asm volatile("cp.async.wait_group 0;" ::: "memory")

#define LDSM4(r, a) \
    asm volatile("ldmatrix.sync.aligned.m8n8.x4.shared.b16 {%0,%1,%2,%3}, [%4];" \
        : "=r"((r)[0]), "=r"((r)[1]), "=r"((r)[2]), "=r"((r)[3]) : "r"(a))
#define LDSM2(r0, r1, a) \
    asm volatile("ldmatrix.sync.aligned.m8n8.x2.shared.b16 {%0,%1}, [%2];" \
        : "=r"(r0), "=r"(r1) : "r"(a))

#define MMA(ar, b0, b1, cc) \
    asm volatile("mma.sync.aligned.m16n8k16.row.col.f32.bf16.bf16.f32 " \
        "{%0,%1,%2,%3}, {%4,%5,%6,%7}, {%8,%9}, {%0,%1,%2,%3};" \
        : "+f"((cc)[0]), "+f"((cc)[1]), "+f"((cc)[2]), "+f"((cc)[3]) \
        : "r"((ar)[0]), "r"((ar)[1]), "r"((ar)[2]), "r"((ar)[3]), "r"(b0), "r"(b1))

// one A frag (m16) x 7 n8 frags
#define PASS(A, B) do { \
    MMA((A), (B)[0], (B)[2],  acc[0]); MMA((A), (B)[1], (B)[3],  acc[1]); \
    MMA((A), (B)[4], (B)[6],  acc[2]); MMA((A), (B)[5], (B)[7],  acc[3]); \
    MMA((A), (B)[8], (B)[10], acc[4]); MMA((A), (B)[9], (B)[11], acc[5]); \
    MMA((A), (B)[12], (B)[13], acc[6]); \
} while (0)

// swizzled smem offset: 64B rows, seg = 16B column (0..3)
__device__ __forceinline__ uint32_t swz(int row, int seg) {
    return (uint32_t)(row * 64 + ((seg ^ ((row >> 1) & 3)) << 4));
}

// ---------------------------------------------------------------------------
// Precompute 1: pad + hi/lo split features -> g_pf_hi/lo [130,130,416]
// ---------------------------------------------------------------------------
__global__ __launch_bounds__(256) void pad_split_features(const float* __restrict__ f)
{
    int idx = blockIdx.x * 256 + threadIdx.x;
    const int TOT = PFW * PFW * (CPAD / 4);
    if (idx >= TOT) return;
    int p = idx / (CPAD / 4);
    int c0 = (idx - p * (CPAD / 4)) * 4;
    int y = p / PFW - 1;
    int x = p - (y + 1) * PFW - 1;
    bool in = ((unsigned)y < HH) && ((unsigned)x < WW);
    uint16_t h[4], l[4];
#pragma unroll
    for (int j = 0; j < 4; ++j) {
        int c = c0 + j;
        float v = (in && c < CC) ? __ldg(f + ((size_t)(y * WW + x)) * CC + c) : 0.f;
        __nv_bfloat16 hb = __float2bfloat16(v);
        float r = v - __bfloat162float(hb);
        __nv_bfloat16 lb = __float2bfloat16(r);
        h[j] = __bfloat16_as_ushort(hb);
        l[j] = __bfloat16_as_ushort(lb);
    }
    size_t o = (size_t)p * CPAD + c0;
    *(uint2*)(g_pf_hi + o) = make_uint2((uint32_t)h[0] | ((uint32_t)h[1] << 16),
                                        (uint32_t)h[2] | ((uint32_t)h[3] << 16));
    *(uint2*)(g_pf_lo + o) = make_uint2((uint32_t)l[0] | ((uint32_t)l[1] << 16),
                                        (uint32_t)l[2] | ((uint32_t)l[3] << 16));
}

// ---------------------------------------------------------------------------
// Precompute 2: coalesced transpose + split weights -> g_wt_hi/lo [392][3744]
// ---------------------------------------------------------------------------
__global__ __launch_bounds__(256) void split_weights(const float* __restrict__ w)
{
    __shared__ float tile[32][33];
    const int tap = blockIdx.z;
    const int ci0 = blockIdx.x * 32;
    const int n0  = blockIdx.y * 32;
    const int tx = threadIdx.x & 31;
    const int ty = threadIdx.x >> 5;
#pragma unroll
    for (int r = 0; r < 4; ++r) {
        int ci = ci0 + ty + r * 8;
        int n  = n0 + tx;
        float v = 0.f;
        if (ci < CC && n < CC) v = __ldg(w + ((size_t)(tap * CC + ci)) * CC + n);
        tile[ty + r * 8][tx] = v;
    }
    __syncthreads();
#pragma unroll
    for (int r = 0; r < 4; ++r) {
        int n  = n0 + ty + r * 8;
        int ci = ci0 + tx;
        if (n < CC && ci < CPAD) {
            float v = (ci < CC) ? tile[tx][ty + r * 8] : 0.f;
            __nv_bfloat16 hb = __float2bfloat16(v);
            float res = v - __bfloat162float(hb);
            size_t o = (size_t)n * KTOT + tap * CPAD + ci;
            g_wt_hi[o] = hb;
            g_wt_lo[o] = __float2bfloat16(res);
        }
    }
}

__global__ __launch_bounds__(256) void pad_weights_tail()
{
    int idx = blockIdx.x * 256 + threadIdx.x;
    const int TOT = CC * 9 * (CPAD - CC);
    if (idx >= TOT) return;
    int n = idx / (9 * (CPAD - CC));
    int rem = idx - n * 9 * (CPAD - CC);
    int tap = rem / (CPAD - CC);
    int ci = CC + rem - tap * (CPAD - CC);
    size_t o = (size_t)n * KTOT + tap * CPAD + ci;
    g_wt_hi[o] = __float2bfloat16(0.f);
    g_wt_lo[o] = __float2bfloat16(0.f);
}

// ---------------------------------------------------------------------------
// Conv implicit GEMM, persistent. Tile: BM=128 (1 row), BN=56. 256 threads,
// 8 warps on M (warp tile 16x56). 3-pass hi/lo (hh -> lh -> hl, minimizes
// live fragments), 3-stage cp.async pipeline (round-9 barrier shape),
// 3 CTAs/SM via launch bounds. XOR swizzle.
// ---------------------------------------------------------------------------
__device__ __forceinline__ void issue_chunk(int c, int s, int tid, int y, int n0, uint32_t sm)
{
    int tap = c / 13;
    int ci0 = (c - tap * 13) * 32;
    int dy = tap / 3 - 1;
    int dx = tap - (tap / 3) * 3 - 1;
    uint32_t sbase = sm + s * STAGE_BYTES;
    // A: 128 rows x 64B x 2 mats = 1024 x 16B over 256 threads
#pragma unroll
    for (int t = 0; t < 4; ++t) {
        int i = tid + t * 256;
        int mat = i >> 9;
        int r = (i >> 2) & 127;
        int seg = i & 3;
        const __nv_bfloat16* g = mat ? g_pf_lo : g_pf_hi;
        const __nv_bfloat16* src = g
            + ((size_t)((y + dy + 1) * PFW + (r + dx + 1))) * CPAD + ci0 + seg * 8;
        uint32_t dst = sbase + mat * 8192 + swz(r, seg);
        CP16(dst, src);
    }
    // B: 56 rows x 64B x 2 mats = 448 x 16B
#pragma unroll
    for (int t = 0; t < 2; ++t) {
        int i = tid + t * 256;
        if (i < 448) {
            int mat = (i >= 224);
            int ii = i - mat * 224;
            int rr = ii >> 2;
            int seg = ii & 3;
            const __nv_bfloat16* g = mat ? g_wt_lo : g_wt_hi;
            const __nv_bfloat16* src = g + (size_t)(n0 + rr) * KTOT + tap * CPAD + ci0 + seg * 8;
            uint32_t dst = sbase + ST_BHI + mat * 3584 + swz(rr, seg);
            CP16(dst, src);
        }
    }
    CP_COMMIT();
}

__global__ void __launch_bounds__(256, 3) conv_mma_kernel()
{
    extern __shared__ char smem[];
    uint32_t sm = smem_u32(smem);
    const int tid  = threadIdx.x;
    const int lane = tid & 31;
    const int wid  = tid >> 5;

    const int l15 = lane & 15;
    const int l7  = lane & 7;
    const int hi16 = lane >> 4;          // 0/1: k-seg select for LDSM4
    const int hi8  = (lane >> 3) & 1;    // k-seg select for LDSM2
    const int arow = wid * 16 + l15;

#pragma unroll 1
    for (int tt = blockIdx.x; tt < NTILES; tt += GRID) {
        const int y  = tt / 7;
        const int n0 = (tt - y * 7) * 56;

        float acc[7][4];
#pragma unroll
        for (int j = 0; j < 7; ++j)
#pragma unroll
            for (int q = 0; q < 4; ++q) acc[j][q] = 0.f;

        issue_chunk(0, 0, tid, y, n0, sm);
        issue_chunk(1, 1, tid, y, n0, sm);
        issue_chunk(2, 2, tid, y, n0, sm);

        int s = 0;
#pragma unroll 1
        for (int c = 0; c < NCH; ++c) {
            if (c < NCH - 2)       { CP_WAIT2(); }
            else if (c == NCH - 2) { CP_WAIT1(); }
            else                   { CP_WAIT0(); }
            __syncthreads();
            const uint32_t st  = sm + s * STAGE_BYTES;
            const uint32_t Ahi = st + ST_AHI;
            const uint32_t Alo = st + ST_ALO;
            const uint32_t Bhi = st + ST_BHI;
            const uint32_t Blo = st + ST_BLO;
#pragma unroll
            for (int ks = 0; ks < 2; ++ks) {
                const int sa = ks * 2 + hi16;
                const int s2 = ks * 2 + hi8;
                uint32_t ah[4], aw[4], bh[14], bl[14];
                const uint32_t aoff = swz(arow, sa);
                // pass order hh -> lh -> hl keeps live-fragment set minimal:
                // {ah,bh} -> {ah,bh,aw} -> {ah,bl}
                LDSM4(ah, Ahi + aoff);
                LDSM4(&bh[0], Bhi + swz(l15, sa));
                LDSM4(&bh[4], Bhi + swz(16 + l15, sa));
                LDSM4(&bh[8], Bhi + swz(32 + l15, sa));
                LDSM2(bh[12], bh[13], Bhi + swz(48 + l7, s2));
                PASS(ah, bh);                       // hi * hi
                LDSM4(aw, Alo + aoff);
                PASS(aw, bh);                       // lo * hi (bh dies here)
                LDSM4(&bl[0], Blo + swz(l15, sa));
                LDSM4(&bl[4], Blo + swz(16 + l15, sa));
                LDSM4(&bl[8], Blo + swz(32 + l15, sa));
                LDSM2(bl[12], bl[13], Blo + swz(48 + l7, s2));
                PASS(ah, bl);                       // hi * lo
            }
            __syncthreads();
            if (c + 3 < NCH) issue_chunk(c + 3, s, tid, y, n0, sm);
            s = (s == 2) ? 0 : s + 1;
        }

        // epilogue: warp tile 16x56 -> g_map[y, x, n]
        {
            const int nlane = n0 + (lane & 3) * 2;
#pragma unroll
            for (int h = 0; h < 2; ++h) {
                const int x = wid * 16 + (lane >> 2) + h * 8;
                float* op = g_map + ((size_t)(y * WW + x)) * CC;
#pragma unroll
                for (int j = 0; j < 7; ++j)
                    *(float2*)(op + nlane + j * 8) =
                        make_float2(acc[j][h * 2], acc[j][h * 2 + 1]);
            }
        }
    }
}

// ---------------------------------------------------------------------------
// Kernel: PS-RoI pool of conv map -> per-bin offsets (feature coords)
// ---------------------------------------------------------------------------
__global__ __launch_bounds__(256) void offset_pool_kernel(const float* __restrict__ rois, int N)
{
    int idx = blockIdx.x * blockDim.x + threadIdx.x;
    if (idx >= N * KK) return;
    int n   = idx / KK;
    int bin = idx - n * KK;
    int bi  = bin / KPOOL;
    int bj  = bin - bi * KPOOL;

    const float* r = rois + n * 5;
    float r1 = r[1], r2 = r[2], r3 = r[3], r4 = r[4];
    float x1 = r1 * 0.0625f;
    float y1 = r2 * 0.0625f;
    float x2 = (r3 + 1.0f) * 0.0625f;
    float y2 = (r4 + 1.0f) * 0.0625f;
    float bw = (x2 - x1) / 7.0f;
    float bh = (y2 - y1) / 7.0f;
    float cx = x1 + ((float)bj + 0.5f) * bw;
    float cy = y1 + ((float)bi + 0.5f) * bh;

    float y0f = floorf(cy), x0f = floorf(cx);
    float wy = cy - y0f,    wx = cx - x0f;
    int iy0 = min(max((int)y0f, 0), HH - 1);
    int iy1 = min(max((int)y0f + 1, 0), HH - 1);
    int ix0 = min(max((int)x0f, 0), WW - 1);
    int ix1 = min(max((int)x0f + 1, 0), WW - 1);

    float w00 = (1.f - wy) * (1.f - wx);
    float w01 = (1.f - wy) * wx;
    float w10 = wy * (1.f - wx);
    float w11 = wy * wx;

    const float* p00 = g_map + ((size_t)(iy0 * WW + ix0)) * CC + bin * 8;
    const float* p01 = g_map + ((size_t)(iy0 * WW + ix1)) * CC + bin * 8;
    const float* p10 = g_map + ((size_t)(iy1 * WW + ix0)) * CC + bin * 8;
    const float* p11 = g_map + ((size_t)(iy1 * WW + ix1)) * CC + bin * 8;

    float rw = r3 - r1 + 1.0f;
    float rh = r4 - r2 + 1.0f;

    float* o = g_off + (size_t)idx * 8;
#pragma unroll
    for (int g = 0; g < 4; ++g) {
        int d0 = g * 2, d1 = g * 2 + 1;
        float px = w00 * p00[d0] + w01 * p01[d0] + w10 * p10[d0] + w11 * p11[d0];
        float py = w00 * p00[d1] + w01 * p01[d1] + w10 * p10[d1] + w11 * p11[d1];
        o[d0] = (px * rw) * 0.1f * 0.0625f;
        o[d1] = (py * rh) * 0.1f * 0.0625f;
    }
}

// ---------------------------------------------------------------------------
// Kernel: deformable PS-RoI pool of raw features -> output [N,8,7,7]
// ---------------------------------------------------------------------------
__global__ __launch_bounds__(256) void deform_pool_kernel(const float* __restrict__ f,
                                                          const float* __restrict__ rois,
                                                          float* __restrict__ out, int N)
{
    int idx = blockIdx.x * blockDim.x + threadIdx.x;
    if (idx >= N * KK * 8) return;
    int d   = idx & 7;
    int nb  = idx >> 3;
    int n   = nb / KK;
    int bin = nb - n * KK;
    int bi  = bin / KPOOL;
    int bj  = bin - bi * KPOOL;

    const float* r = rois + n * 5;
    float x1 = r[1] * 0.0625f;
    float y1 = r[2] * 0.0625f;
    float x2 = (r[3] + 1.0f) * 0.0625f;
    float y2 = (r[4] + 1.0f) * 0.0625f;
    float bw = (x2 - x1) / 7.0f;
    float bh = (y2 - y1) / 7.0f;
    float cx = x1 + ((float)bj + 0.5f) * bw;
    float cy = y1 + ((float)bi + 0.5f) * bh;

    int g = d >> 1;
    const float* o = g_off + (size_t)nb * 8 + g * 2;
    float sx = cx + o[0];
    float sy = cy + o[1];

    float y0f = floorf(sy), x0f = floorf(sx);
    float wy = sy - y0f,    wx = sx - x0f;
    int iy0 = min(max((int)y0f, 0), HH - 1);
    int iy1 = min(max((int)y0f + 1, 0), HH - 1);
    int ix0 = min(max((int)x0f, 0), WW - 1);
    int ix1 = min(max((int)x0f + 1, 0), WW - 1);

    int ch = bin * 8 + d;
    float v00 = __ldg(f + ((size_t)(iy0 * WW + ix0)) * CC + ch);
    float v01 = __ldg(f + ((size_t)(iy0 * WW + ix1)) * CC + ch);
    float v10 = __ldg(f + ((size_t)(iy1 * WW + ix0)) * CC + ch);
    float v11 = __ldg(f + ((size_t)(iy1 * WW + ix1)) * CC + ch);

    float val = (1.f - wy) * (1.f - wx) * v00 + (1.f - wy) * wx * v01
              + wy * (1.f - wx) * v10 + wy * wx * v11;

    out[((size_t)n * 8 + d) * KK + bin] = val;
}

// ---------------------------------------------------------------------------
extern "C" void kernel_launch(void* const* d_in, const int* in_sizes, int n_in,
                              void* d_out, int out_size)
{
    const float* features = (const float*)d_in[0];  // [1,128,128,392]
    const float* rois     = (const float*)d_in[1];  // [N,5]
    const float* conv_w   = (const float*)d_in[2];  // [3,3,392,392]
    float* out = (float*)d_out;
    int N = in_sizes[1] / 5;

    cudaFuncSetAttribute(conv_mma_kernel, cudaFuncAttributeMaxDynamicSharedMemorySize, SMEM_BYTES);

    {
        int tot = PFW * PFW * (CPAD / 4);
        pad_split_features<<<(tot + 255) / 256, 256>>>(features);
        dim3 gw(13, 13, 9);
        split_weights<<<gw, 256>>>(conv_w);
        int pt = CC * 9 * (CPAD - CC);
        pad_weights_tail<<<(pt + 255) / 256, 256>>>();
    }

    conv_mma_kernel<<<GRID, 256, SMEM_BYTES>>>();

    int t2 = N * KK;
    offset_pool_kernel<<<(t2 + 255) / 256, 256>>>(rois, N);

    int t3 = N * KK * 8;
    deform_pool_kernel<<<(t3 + 255) / 256, 256>>>(features, rois, out, N);
}

// round 13
// speedup vs baseline: 2.5600x; 1.0398x over previous
#include <cuda_runtime.h>
#include <cuda_bf16.h>
#include <cstdint>

#define HH 128
#define WW 128
#define CC 392
#define KPOOL 7
#define KK 49
#define MAXN 2048

#define CPAD 416              // channels padded (13 x 32)
#define PFW 130               // padded spatial (halo 1)
#define KTOT (9 * CPAD)       // 3744
#define NCH 117               // 9 taps * 13 ci-blocks of 32

#define PFAREA (PFW * PFW * CPAD)   // one matrix (hi or lo) of padded features
#define WTAREA (CC * KTOT)          // one matrix of weights

#define NTILES 896            // 128 M-tiles (rows) x 7 N-tiles (56)
#define GRID 444              // 148 SMs x 3 CTAs

// smem per stage (bytes): A_hi[128*64] A_lo[128*64] B_hi[56*64] B_lo[56*64]
#define ST_AHI 0
#define ST_ALO 8192
#define ST_BHI 16384
#define ST_BLO 19968
#define STAGE_BYTES 23552
#define SMEM_BYTES (3 * STAGE_BYTES)

// ---------------------------------------------------------------------------
// Device scratch (no allocation allowed). hi matrix at [0], lo at [AREA].
// ---------------------------------------------------------------------------
__device__ __nv_bfloat16 g_pf[2 * PFAREA];
__device__ __nv_bfloat16 g_wt[2 * WTAREA];
__device__ float g_map[HH * WW * CC];
__device__ float g_off[MAXN * KK * 8];

// ---------------------------------------------------------------------------
// PTX helpers (baseline sm_80-era — safe for compute_103)
// ---------------------------------------------------------------------------
__device__ __forceinline__ uint32_t smem_u32(const void* p) {
    uint32_t a;
    asm("{ .reg .u64 t; cvta.to.shared.u64 t, %1; cvt.u32.u64 %0, t; }" : "=r"(a) : "l"(p));
    return a;
}
#define CP16(dst, src) \
    asm volatile("cp.async.cg.shared.global [%0], [%1], 16;" :: "r"(dst), "l"(src))
#define CP_COMMIT() asm volatile("cp.async.commit_group;" ::: "memory")
#define CP_WAIT2() asm volatile("cp.async.wait_group 2;" ::: "memory")
#define CP_WAIT1() asm volatile("cp.async.wait_group 1;" ::: "memory")
#define CP_WAIT0() asm volatile("cp.async.wait_group 0;" ::: "memory")

#define LDSM4(r, a) \
    asm volatile("ldmatrix.sync.aligned.m8n8.x4.shared.b16 {%0,%1,%2,%3}, [%4];" \
        : "=r"((r)[0]), "=r"((r)[1]), "=r"((r)[2]), "=r"((r)[3]) : "r"(a))
#define LDSM2(r0, r1, a) \
    asm volatile("ldmatrix.sync.aligned.m8n8.x2.shared.b16 {%0,%1}, [%2];" \
        : "=r"(r0), "=r"(r1) : "r"(a))

#define MMA(ar, b0, b1, cc) \
    asm volatile("mma.sync.aligned.m16n8k16.row.col.f32.bf16.bf16.f32 " \
        "{%0,%1,%2,%3}, {%4,%5,%6,%7}, {%8,%9}, {%0,%1,%2,%3};" \
        : "+f"((cc)[0]), "+f"((cc)[1]), "+f"((cc)[2]), "+f"((cc)[3]) \
        : "r"((ar)[0]), "r"((ar)[1]), "r"((ar)[2]), "r"((ar)[3]), "r"(b0), "r"(b1))

// one A frag (m16) x 7 n8 frags
#define PASS(A, B) do { \
    MMA((A), (B)[0], (B)[2],  acc[0]); MMA((A), (B)[1], (B)[3],  acc[1]); \
    MMA((A), (B)[4], (B)[6],  acc[2]); MMA((A), (B)[5], (B)[7],  acc[3]); \
    MMA((A), (B)[8], (B)[10], acc[4]); MMA((A), (B)[9], (B)[11], acc[5]); \
    MMA((A), (B)[12], (B)[13], acc[6]); \
} while (0)

// swizzled smem offset: 64B rows, seg = 16B column (0..3)
__device__ __forceinline__ uint32_t swz(int row, int seg) {
    return (uint32_t)(row * 64 + ((seg ^ ((row >> 1) & 3)) << 4));
}

// ---------------------------------------------------------------------------
// Precompute 1: pad + hi/lo split features -> g_pf [2][130,130,416]
// ---------------------------------------------------------------------------
__global__ __launch_bounds__(256) void pad_split_features(const float* __restrict__ f)
{
    int idx = blockIdx.x * 256 + threadIdx.x;
    const int TOT = PFW * PFW * (CPAD / 4);
    if (idx >= TOT) return;
    int p = idx / (CPAD / 4);
    int c0 = (idx - p * (CPAD / 4)) * 4;
    int y = p / PFW - 1;
    int x = p - (y + 1) * PFW - 1;
    bool in = ((unsigned)y < HH) && ((unsigned)x < WW);
    uint16_t h[4], l[4];
#pragma unroll
    for (int j = 0; j < 4; ++j) {
        int c = c0 + j;
        float v = (in && c < CC) ? __ldg(f + ((size_t)(y * WW + x)) * CC + c) : 0.f;
        __nv_bfloat16 hb = __float2bfloat16(v);
        float r = v - __bfloat162float(hb);
        __nv_bfloat16 lb = __float2bfloat16(r);
        h[j] = __bfloat16_as_ushort(hb);
        l[j] = __bfloat16_as_ushort(lb);
    }
    size_t o = (size_t)p * CPAD + c0;
    *(uint2*)(g_pf + o) = make_uint2((uint32_t)h[0] | ((uint32_t)h[1] << 16),
                                     (uint32_t)h[2] | ((uint32_t)h[3] << 16));
    *(uint2*)(g_pf + PFAREA + o) = make_uint2((uint32_t)l[0] | ((uint32_t)l[1] << 16),
                                              (uint32_t)l[2] | ((uint32_t)l[3] << 16));
}

// ---------------------------------------------------------------------------
// Precompute 2: coalesced transpose + split weights -> g_wt [2][392][3744]
// ---------------------------------------------------------------------------
__global__ __launch_bounds__(256) void split_weights(const float* __restrict__ w)
{
    __shared__ float tile[32][33];
    const int tap = blockIdx.z;
    const int ci0 = blockIdx.x * 32;
    const int n0  = blockIdx.y * 32;
    const int tx = threadIdx.x & 31;
    const int ty = threadIdx.x >> 5;
#pragma unroll
    for (int r = 0; r < 4; ++r) {
        int ci = ci0 + ty + r * 8;
        int n  = n0 + tx;
        float v = 0.f;
        if (ci < CC && n < CC) v = __ldg(w + ((size_t)(tap * CC + ci)) * CC + n);
        tile[ty + r * 8][tx] = v;
    }
    __syncthreads();
#pragma unroll
    for (int r = 0; r < 4; ++r) {
        int n  = n0 + ty + r * 8;
        int ci = ci0 + tx;
        if (n < CC && ci < CPAD) {
            float v = (ci < CC) ? tile[tx][ty + r * 8] : 0.f;
            __nv_bfloat16 hb = __float2bfloat16(v);
            float res = v - __bfloat162float(hb);
            size_t o = (size_t)n * KTOT + tap * CPAD + ci;
            g_wt[o] = hb;
            g_wt[WTAREA + o] = __float2bfloat16(res);
        }
    }
}

__global__ __launch_bounds__(256) void pad_weights_tail()
{
    int idx = blockIdx.x * 256 + threadIdx.x;
    const int TOT = CC * 9 * (CPAD - CC);
    if (idx >= TOT) return;
    int n = idx / (9 * (CPAD - CC));
    int rem = idx - n * 9 * (CPAD - CC);
    int tap = rem / (CPAD - CC);
    int ci = CC + rem - tap * (CPAD - CC);
    size_t o = (size_t)n * KTOT + tap * CPAD + ci;
    g_wt[o] = __float2bfloat16(0.f);
    g_wt[WTAREA + o] = __float2bfloat16(0.f);
}

// ---------------------------------------------------------------------------
// Conv implicit GEMM, persistent. Tile: BM=128 (1 row), BN=56. 256 threads,
// 8 warps on M (warp tile 16x56). 3-pass hi/lo (hh -> lh -> hl), 3-stage
// cp.async pipeline, 3 CTAs/SM. ALL per-chunk addressing hoisted into
// per-thread constants + 2 incrementally-maintained uniforms.
// ---------------------------------------------------------------------------
__global__ void __launch_bounds__(256, 3) conv_mma_kernel()
{
    extern __shared__ char smem[];
    uint32_t sm = smem_u32(smem);
    const int tid  = threadIdx.x;
    const int lane = tid & 31;
    const int wid  = tid >> 5;

    const int l15 = lane & 15;
    const int l7  = lane & 7;
    const int hi16 = lane >> 4;          // 0/1: k-seg select for LDSM4
    const int hi8  = (lane >> 3) & 1;    // k-seg select for LDSM2
    const int arow = wid * 16 + l15;

    // ---- per-thread cp.async constants ----
    int aoff_e[4]; uint32_t adst[4];
#pragma unroll
    for (int t = 0; t < 4; ++t) {
        int i = tid + t * 256;
        int mat = i >> 9;
        int r = (i >> 2) & 127;
        int seg = i & 3;
        aoff_e[t] = mat * PFAREA + r * CPAD + seg * 8;
        adst[t] = (uint32_t)(mat * 8192) + swz(r, seg);
    }
    int boff_e[2]; uint32_t bdst[2];
#pragma unroll
    for (int t = 0; t < 2; ++t) {
        int i = tid + t * 256;
        int mat = (i >= 224);
        int ii = i - mat * 224;
        int rr = ii >> 2;
        int seg = ii & 3;
        boff_e[t] = mat * WTAREA + rr * KTOT + seg * 8;
        bdst[t] = (uint32_t)(ST_BHI + mat * 3584) + swz(rr, seg);
    }
    const bool bact1 = (tid < 192);      // second B quarter-wave active?

    // ---- per-thread LDSM offsets (per ks) ----
    uint32_t aof[2], bof0[2], bof1[2], bof2[2], bof3[2];
#pragma unroll
    for (int ks = 0; ks < 2; ++ks) {
        int sa = ks * 2 + hi16;
        int s2 = ks * 2 + hi8;
        aof[ks]  = ST_AHI + swz(arow, sa);
        bof0[ks] = ST_BHI + swz(l15, sa);
        bof1[ks] = ST_BHI + swz(16 + l15, sa);
        bof2[ks] = ST_BHI + swz(32 + l15, sa);
        bof3[ks] = ST_BHI + swz(48 + l7, s2);
    }

#define ISSUE_CHUNK(sidx) do {                                                \
    uint32_t sb = sm + (sidx) * STAGE_BYTES;                                  \
    CP16(sb + adst[0], g_pf + (size_t)(au + aoff_e[0]));                      \
    CP16(sb + adst[1], g_pf + (size_t)(au + aoff_e[1]));                      \
    CP16(sb + adst[2], g_pf + (size_t)(au + aoff_e[2]));                      \
    CP16(sb + adst[3], g_pf + (size_t)(au + aoff_e[3]));                      \
    CP16(sb + bdst[0], g_wt + (size_t)(bu + boff_e[0]));                      \
    if (bact1) CP16(sb + bdst[1], g_wt + (size_t)(bu + boff_e[1]));           \
    CP_COMMIT();                                                              \
    if (++pf_ci == 13) {                                                      \
        pf_ci = 0; ++pf_tap;                                                  \
        int dyv = pf_tap / 3 - 1;                                             \
        int dxv = pf_tap - (pf_tap / 3) * 3 - 1;                              \
        au = ((y + dyv + 1) * PFW + (dxv + 1)) * CPAD;                        \
        bu = n0 * KTOT + pf_tap * CPAD;                                       \
    } else { au += 32; bu += 32; }                                            \
} while (0)

#pragma unroll 1
    for (int tt = blockIdx.x; tt < NTILES; tt += GRID) {
        const int y  = tt / 7;
        const int n0 = (tt - y * 7) * 56;

        float acc[7][4];
#pragma unroll
        for (int j = 0; j < 7; ++j)
#pragma unroll
            for (int q = 0; q < 4; ++q) acc[j][q] = 0.f;

        // prefetch state: tap 0 => dy=-1, dx=-1
        int pf_tap = 0, pf_ci = 0;
        int au = (y * PFW) * CPAD;       // ((y-1)+1)*PFW + (-1+1) = y*PFW
        int bu = n0 * KTOT;

        ISSUE_CHUNK(0);
        ISSUE_CHUNK(1);
        ISSUE_CHUNK(2);

        int s = 0;
#pragma unroll 1
        for (int c = 0; c < NCH; ++c) {
            if (c < NCH - 2)       { CP_WAIT2(); }
            else if (c == NCH - 2) { CP_WAIT1(); }
            else                   { CP_WAIT0(); }
            __syncthreads();
            const uint32_t st = sm + s * STAGE_BYTES;
#pragma unroll
            for (int ks = 0; ks < 2; ++ks) {
                uint32_t ah[4], aw[4], bh[14], bl[14];
                const uint32_t a_hi = st + aof[ks];
                // pass order hh -> lh -> hl keeps live-fragment set minimal
                LDSM4(ah, a_hi);
                LDSM4(&bh[0], st + bof0[ks]);
                LDSM4(&bh[4], st + bof1[ks]);
                LDSM4(&bh[8], st + bof2[ks]);
                LDSM2(bh[12], bh[13], st + bof3[ks]);
                PASS(ah, bh);                       // hi * hi
                LDSM4(aw, a_hi + (ST_ALO - ST_AHI));
                PASS(aw, bh);                       // lo * hi (bh dies here)
                LDSM4(&bl[0], st + bof0[ks] + (ST_BLO - ST_BHI));
                LDSM4(&bl[4], st + bof1[ks] + (ST_BLO - ST_BHI));
                LDSM4(&bl[8], st + bof2[ks] + (ST_BLO - ST_BHI));
                LDSM2(bl[12], bl[13], st + bof3[ks] + (ST_BLO - ST_BHI));
                PASS(ah, bl);                       // hi * lo
            }
            __syncthreads();
            if (c + 3 < NCH) ISSUE_CHUNK(s);
            s = (s == 2) ? 0 : s + 1;
        }

        // epilogue: warp tile 16x56 -> g_map[y, x, n]
        {
            const int nlane = n0 + (lane & 3) * 2;
#pragma unroll
            for (int h = 0; h < 2; ++h) {
                const int x = wid * 16 + (lane >> 2) + h * 8;
                float* op = g_map + ((size_t)(y * WW + x)) * CC;
#pragma unroll
                for (int j = 0; j < 7; ++j)
                    *(float2*)(op + nlane + j * 8) =
                        make_float2(acc[j][h * 2], acc[j][h * 2 + 1]);
            }
        }
    }
#undef ISSUE_CHUNK
}

// ---------------------------------------------------------------------------
// Kernel: PS-RoI pool of conv map -> per-bin offsets (feature coords)
// ---------------------------------------------------------------------------
__global__ __launch_bounds__(256) void offset_pool_kernel(const float* __restrict__ rois, int N)
{
    int idx = blockIdx.x * blockDim.x + threadIdx.x;
    if (idx >= N * KK) return;
    int n   = idx / KK;
    int bin = idx - n * KK;
    int bi  = bin / KPOOL;
    int bj  = bin - bi * KPOOL;

    const float* r = rois + n * 5;
    float r1 = r[1], r2 = r[2], r3 = r[3], r4 = r[4];
    float x1 = r1 * 0.0625f;
    float y1 = r2 * 0.0625f;
    float x2 = (r3 + 1.0f) * 0.0625f;
    float y2 = (r4 + 1.0f) * 0.0625f;
    float bw = (x2 - x1) / 7.0f;
    float bh = (y2 - y1) / 7.0f;
    float cx = x1 + ((float)bj + 0.5f) * bw;
    float cy = y1 + ((float)bi + 0.5f) * bh;

    float y0f = floorf(cy), x0f = floorf(cx);
    float wy = cy - y0f,    wx = cx - x0f;
    int iy0 = min(max((int)y0f, 0), HH - 1);
    int iy1 = min(max((int)y0f + 1, 0), HH - 1);
    int ix0 = min(max((int)x0f, 0), WW - 1);
    int ix1 = min(max((int)x0f + 1, 0), WW - 1);

    float w00 = (1.f - wy) * (1.f - wx);
    float w01 = (1.f - wy) * wx;
    float w10 = wy * (1.f - wx);
    float w11 = wy * wx;

    const float* p00 = g_map + ((size_t)(iy0 * WW + ix0)) * CC + bin * 8;
    const float* p01 = g_map + ((size_t)(iy0 * WW + ix1)) * CC + bin * 8;
    const float* p10 = g_map + ((size_t)(iy1 * WW + ix0)) * CC + bin * 8;
    const float* p11 = g_map + ((size_t)(iy1 * WW + ix1)) * CC + bin * 8;

    float rw = r3 - r1 + 1.0f;
    float rh = r4 - r2 + 1.0f;

    float* o = g_off + (size_t)idx * 8;
#pragma unroll
    for (int g = 0; g < 4; ++g) {
        int d0 = g * 2, d1 = g * 2 + 1;
        float px = w00 * p00[d0] + w01 * p01[d0] + w10 * p10[d0] + w11 * p11[d0];
        float py = w00 * p00[d1] + w01 * p01[d1] + w10 * p10[d1] + w11 * p11[d1];
        o[d0] = (px * rw) * 0.1f * 0.0625f;
        o[d1] = (py * rh) * 0.1f * 0.0625f;
    }
}

// ---------------------------------------------------------------------------
// Kernel: deformable PS-RoI pool of raw features -> output [N,8,7,7]
// ---------------------------------------------------------------------------
__global__ __launch_bounds__(256) void deform_pool_kernel(const float* __restrict__ f,
                                                          const float* __restrict__ rois,
                                                          float* __restrict__ out, int N)
{
    int idx = blockIdx.x * blockDim.x + threadIdx.x;
    if (idx >= N * KK * 8) return;
    int d   = idx & 7;
    int nb  = idx >> 3;
    int n   = nb / KK;
    int bin = nb - n * KK;
    int bi  = bin / KPOOL;
    int bj  = bin - bi * KPOOL;

    const float* r = rois + n * 5;
    float x1 = r[1] * 0.0625f;
    float y1 = r[2] * 0.0625f;
    float x2 = (r[3] + 1.0f) * 0.0625f;
    float y2 = (r[4] + 1.0f) * 0.0625f;
    float bw = (x2 - x1) / 7.0f;
    float bh = (y2 - y1) / 7.0f;
    float cx = x1 + ((float)bj + 0.5f) * bw;
    float cy = y1 + ((float)bi + 0.5f) * bh;

    int g = d >> 1;
    const float* o = g_off + (size_t)nb * 8 + g * 2;
    float sx = cx + o[0];
    float sy = cy + o[1];

    float y0f = floorf(sy), x0f = floorf(sx);
    float wy = sy - y0f,    wx = sx - x0f;
    int iy0 = min(max((int)y0f, 0), HH - 1);
    int iy1 = min(max((int)y0f + 1, 0), HH - 1);
    int ix0 = min(max((int)x0f, 0), WW - 1);
    int ix1 = min(max((int)x0f + 1, 0), WW - 1);

    int ch = bin * 8 + d;
    float v00 = __ldg(f + ((size_t)(iy0 * WW + ix0)) * CC + ch);
    float v01 = __ldg(f + ((size_t)(iy0 * WW + ix1)) * CC + ch);
    float v10 = __ldg(f + ((size_t)(iy1 * WW + ix0)) * CC + ch);
    float v11 = __ldg(f + ((size_t)(iy1 * WW + ix1)) * CC + ch);

    float val = (1.f - wy) * (1.f - wx) * v00 + (1.f - wy) * wx * v01
              + wy * (1.f - wx) * v10 + wy * wx * v11;

    out[((size_t)n * 8 + d) * KK + bin] = val;
}

// ---------------------------------------------------------------------------
extern "C" void kernel_launch(void* const* d_in, const int* in_sizes, int n_in,
                              void* d_out, int out_size)
{
    const float* features = (const float*)d_in[0];  // [1,128,128,392]
    const float* rois     = (const float*)d_in[1];  // [N,5]
    const float* conv_w   = (const float*)d_in[2];  // [3,3,392,392]
    float* out = (float*)d_out;
    int N = in_sizes[1] / 5;

    cudaFuncSetAttribute(conv_mma_kernel, cudaFuncAttributeMaxDynamicSharedMemorySize, SMEM_BYTES);

    {
        int tot = PFW * PFW * (CPAD / 4);
        pad_split_features<<<(tot + 255) / 256, 256>>>(features);
        dim3 gw(13, 13, 9);
        split_weights<<<gw, 256>>>(conv_w);
        int pt = CC * 9 * (CPAD - CC);
        pad_weights_tail<<<(pt + 255) / 256, 256>>>();
    }

    conv_mma_kernel<<<GRID, 256, SMEM_BYTES>>>();

    int t2 = N * KK;
    offset_pool_kernel<<<(t2 + 255) / 256, 256>>>(rois, N);

    int t3 = N * KK * 8;
    deform_pool_kernel<<<(t3 + 255) / 256, 256>>>(features, rois, out, N);
}